// round 2
// baseline (speedup 1.0000x reference)
#include <cuda_runtime.h>
#include <cuda_bf16.h>
#include <math.h>

// Problem constants
#define NN 100000
#define IN_DIM 500
#define HID 128
#define OUTD 40

// ---------------- scratch (device globals; allocation-free rule) -------------
__device__ int   g_stride;                 // 1 = int32 edges, 2 = int64 edges (read low words)
__device__ int   g_deg [NN];
__device__ float g_dinv[NN];
__device__ __align__(16) float g_h1  [(size_t)NN * HID];
__device__ __align__(16) float g_agg1[(size_t)NN * HID];
__device__ __align__(16) float g_h2  [(size_t)NN * OUTD];
__device__ __align__(16) float g_agg2[(size_t)NN * OUTD];

// ---------------- dtype detect ----------------------------------------------
__global__ void k_detect(const int* __restrict__ e) {
    if (threadIdx.x == 0 && blockIdx.x == 0) {
        int o = 0;
        #pragma unroll
        for (int i = 0; i < 8; i++) o |= e[2 * i + 1];   // high words if int64
        g_stride = (o == 0) ? 2 : 1;
    }
}

// ---------------- degree ----------------------------------------------------
__global__ void k_deginit(int n) {
    int i = blockIdx.x * blockDim.x + threadIdx.x;
    if (i < n) g_deg[i] = 1;                 // self loop
}

__global__ void k_degcount(const int* __restrict__ e, int E) {
    int i = blockIdx.x * blockDim.x + threadIdx.x;
    if (i >= E) return;
    int st = g_stride;
    int dst = e[(size_t)(E + i) * st];
    atomicAdd(&g_deg[dst], 1);
}

__global__ void k_dinv(int n) {
    int i = blockIdx.x * blockDim.x + threadIdx.x;
    if (i < n) g_dinv[i] = rsqrtf((float)g_deg[i]);
}

// ---------------- GEMM1: h1 = x @ W1   (M x 500) * (500 x 128) ---------------
#define G1_BM 128
#define G1_BN 128
#define G1_BK 8
__global__ __launch_bounds__(256, 2)
void k_gemm1(const float* __restrict__ A, const float* __restrict__ B, int M) {
    __shared__ float As[G1_BK][G1_BM];
    __shared__ float Bs[G1_BK][G1_BN];
    const int K = IN_DIM;
    int tid = threadIdx.x;
    int blockRow = blockIdx.x * G1_BM;

    int tx = tid & 15;           // 16 cols of 8
    int ty = tid >> 4;           // 16 rows of 8
    float acc[8][8];
    #pragma unroll
    for (int i = 0; i < 8; i++)
        #pragma unroll
        for (int j = 0; j < 8; j++) acc[i][j] = 0.f;

    int arow = tid >> 1;             // 0..127
    int aq   = (tid & 1) * 4;        // 0 or 4
    int brow = tid >> 5;             // 0..7
    int bq   = (tid & 31) * 4;       // 0..124
    int gRowA = blockRow + arow;

    for (int kt = 0; kt < K; kt += G1_BK) {
        float4 av = make_float4(0.f, 0.f, 0.f, 0.f);
        if (gRowA < M) {
            int kk = kt + aq;
            if (kk + 3 < K) {
                av = *reinterpret_cast<const float4*>(A + (size_t)gRowA * K + kk);
            } else {
                float t[4] = {0.f, 0.f, 0.f, 0.f};
                #pragma unroll
                for (int i = 0; i < 4; i++) if (kk + i < K) t[i] = A[(size_t)gRowA * K + kk + i];
                av = make_float4(t[0], t[1], t[2], t[3]);
            }
        }
        As[aq + 0][arow] = av.x; As[aq + 1][arow] = av.y;
        As[aq + 2][arow] = av.z; As[aq + 3][arow] = av.w;

        float4 bv = make_float4(0.f, 0.f, 0.f, 0.f);
        if (kt + brow < K) bv = *reinterpret_cast<const float4*>(B + (size_t)(kt + brow) * G1_BN + bq);
        *reinterpret_cast<float4*>(&Bs[brow][bq]) = bv;

        __syncthreads();
        #pragma unroll
        for (int k = 0; k < G1_BK; k++) {
            float a[8], b[8];
            #pragma unroll
            for (int i = 0; i < 8; i++) a[i] = As[k][ty * 8 + i];
            #pragma unroll
            for (int j = 0; j < 8; j++) b[j] = Bs[k][tx * 8 + j];
            #pragma unroll
            for (int i = 0; i < 8; i++)
                #pragma unroll
                for (int j = 0; j < 8; j++) acc[i][j] += a[i] * b[j];
        }
        __syncthreads();
    }
    #pragma unroll
    for (int i = 0; i < 8; i++) {
        int r = blockRow + ty * 8 + i;
        if (r < M) {
            #pragma unroll
            for (int j = 0; j < 8; j += 4) {
                *reinterpret_cast<float4*>(g_h1 + (size_t)r * G1_BN + tx * 8 + j) =
                    make_float4(acc[i][j], acc[i][j + 1], acc[i][j + 2], acc[i][j + 3]);
            }
        }
    }
}

// ---------------- self-loop init: agg = h * dinv^2 ---------------------------
// NOTE: these reference the device globals DIRECTLY (never pass __device__
// symbols as host-side kernel args — on GB300 ATS that silently dereferences
// the host shadow copy).
__global__ void k_selfinit1(int n) {
    int i = blockIdx.x * blockDim.x + threadIdx.x;   // over n * 32 float4s
    if (i >= n * (HID / 4)) return;
    int node = i >> 5;
    float s = g_dinv[node]; s *= s;
    float4 v = reinterpret_cast<const float4*>(g_h1)[i];
    v.x *= s; v.y *= s; v.z *= s; v.w *= s;
    reinterpret_cast<float4*>(g_agg1)[i] = v;
}

__global__ void k_selfinit2(int n) {
    int i = blockIdx.x * blockDim.x + threadIdx.x;   // over n * 10 float4s
    if (i >= n * (OUTD / 4)) return;
    int node = i / (OUTD / 4);
    float s = g_dinv[node]; s *= s;
    float4 v = reinterpret_cast<const float4*>(g_h2)[i];
    v.x *= s; v.y *= s; v.z *= s; v.w *= s;
    reinterpret_cast<float4*>(g_agg2)[i] = v;
}

// ---------------- edge propagation, F=128: one warp per edge -----------------
__global__ __launch_bounds__(256)
void k_prop1(const int* __restrict__ e, int E) {
    int warpId = (blockIdx.x * blockDim.x + threadIdx.x) >> 5;
    int lane = threadIdx.x & 31;
    if (warpId >= E) return;
    int st = g_stride;
    int src = e[(size_t)warpId * st];
    int dst = e[(size_t)(E + warpId) * st];
    float nrm = g_dinv[src] * g_dinv[dst];
    float4 v = reinterpret_cast<const float4*>(g_h1 + (size_t)src * HID)[lane];
    v.x *= nrm; v.y *= nrm; v.z *= nrm; v.w *= nrm;
    float* dp = g_agg1 + (size_t)dst * HID + lane * 4;
    asm volatile("red.global.add.v4.f32 [%0], {%1,%2,%3,%4};"
                 :: "l"(dp), "f"(v.x), "f"(v.y), "f"(v.z), "f"(v.w) : "memory");
}

// ---------------- bias + relu (writes back into g_h1) ------------------------
__global__ void k_bias_relu(const float* __restrict__ b1, int n) {
    int i = blockIdx.x * blockDim.x + threadIdx.x;   // over n * 32 float4s
    if (i >= n * (HID / 4)) return;
    int c4 = (i & 31) * 4;
    float4 v = reinterpret_cast<const float4*>(g_agg1)[i];
    float4 b = *reinterpret_cast<const float4*>(b1 + c4);
    v.x = fmaxf(v.x + b.x, 0.f); v.y = fmaxf(v.y + b.y, 0.f);
    v.z = fmaxf(v.z + b.z, 0.f); v.w = fmaxf(v.w + b.w, 0.f);
    reinterpret_cast<float4*>(g_h1)[i] = v;
}

// ---------------- GEMM2: h2 = relu(h) @ W2  (M x 128)*(128 x 40) -------------
__global__ __launch_bounds__(320)
void k_gemm2(const float* __restrict__ W2, int M) {
    __shared__ __align__(16) float sW[HID * OUTD];   // 20 KB
    int tid = threadIdx.x;
    for (int i = tid; i < HID * OUTD; i += 320) sW[i] = W2[i];
    __syncthreads();

    int g = tid % 10;                 // col group (4 cols)
    int rl = tid / 10;                // 0..31
    int row = blockIdx.x * 32 + rl;
    if (row >= M) return;
    const float* hr = g_h1 + (size_t)row * HID;
    float4 acc = make_float4(0.f, 0.f, 0.f, 0.f);
    #pragma unroll 8
    for (int k = 0; k < HID; k++) {
        float hv = __ldg(hr + k);
        float4 w = *reinterpret_cast<const float4*>(&sW[k * OUTD + g * 4]);
        acc.x += hv * w.x; acc.y += hv * w.y; acc.z += hv * w.z; acc.w += hv * w.w;
    }
    *reinterpret_cast<float4*>(g_h2 + (size_t)row * OUTD + g * 4) = acc;
}

// ---------------- edge propagation, F=40: thread per (edge, float4) ----------
__global__ __launch_bounds__(256)
void k_prop2(const int* __restrict__ e, int E) {
    int idx = blockIdx.x * blockDim.x + threadIdx.x;
    if (idx >= E * 10) return;
    int ed = idx / 10;
    int g = idx - ed * 10;
    int st = g_stride;
    int src = e[(size_t)ed * st];
    int dst = e[(size_t)(E + ed) * st];
    float nrm = g_dinv[src] * g_dinv[dst];
    float4 v = reinterpret_cast<const float4*>(g_h2 + (size_t)src * OUTD)[g];
    v.x *= nrm; v.y *= nrm; v.z *= nrm; v.w *= nrm;
    float* dp = g_agg2 + (size_t)dst * OUTD + g * 4;
    asm volatile("red.global.add.v4.f32 [%0], {%1,%2,%3,%4};"
                 :: "l"(dp), "f"(v.x), "f"(v.y), "f"(v.z), "f"(v.w) : "memory");
}

// ---------------- bias + log_softmax: warp per row ---------------------------
__global__ __launch_bounds__(256)
void k_lsm(const float* __restrict__ b2, float* __restrict__ out, int n) {
    int row = (blockIdx.x * blockDim.x + threadIdx.x) >> 5;
    int lane = threadIdx.x & 31;
    if (row >= n) return;
    const float* a = g_agg2 + (size_t)row * OUTD;
    float v0 = a[lane] + b2[lane];                                  // lanes 0..31 valid
    float v1 = (lane < 8) ? (a[lane + 32] + b2[lane + 32]) : -INFINITY;
    float m = fmaxf(v0, v1);
    #pragma unroll
    for (int o = 16; o; o >>= 1) m = fmaxf(m, __shfl_xor_sync(0xffffffffu, m, o));
    float s = expf(v0 - m) + ((lane < 8) ? expf(v1 - m) : 0.f);
    #pragma unroll
    for (int o = 16; o; o >>= 1) s += __shfl_xor_sync(0xffffffffu, s, o);
    float l = m + logf(s);
    out[(size_t)row * OUTD + lane] = v0 - l;
    if (lane < 8) out[(size_t)row * OUTD + 32 + lane] = v1 - l;
}

// ---------------- launch -----------------------------------------------------
extern "C" void kernel_launch(void* const* d_in, const int* in_sizes, int n_in,
                              void* d_out, int out_size) {
    const float* x  = (const float*)d_in[0];
    const int*   e  = (const int*)d_in[1];
    const float* W1 = (const float*)d_in[2];
    const float* b1 = (const float*)d_in[3];
    const float* W2 = (const float*)d_in[4];
    const float* b2 = (const float*)d_in[5];
    float* out = (float*)d_out;

    int N = in_sizes[0] / IN_DIM;     // 100000
    int E = in_sizes[1] / 2;          // 1600000

    k_detect<<<1, 32>>>(e);
    k_deginit<<<(N + 255) / 256, 256>>>(N);
    k_degcount<<<(E + 255) / 256, 256>>>(e, E);
    k_dinv<<<(N + 255) / 256, 256>>>(N);

    k_gemm1<<<(N + G1_BM - 1) / G1_BM, 256>>>(x, W1, N);

    int t1 = N * (HID / 4);
    k_selfinit1<<<(t1 + 255) / 256, 256>>>(N);
    long long p1 = (long long)E * 32;
    k_prop1<<<(int)((p1 + 255) / 256), 256>>>(e, E);
    k_bias_relu<<<(t1 + 255) / 256, 256>>>(b1, N);

    k_gemm2<<<(N + 31) / 32, 320>>>(W2, N);

    int t2 = N * (OUTD / 4);
    k_selfinit2<<<(t2 + 255) / 256, 256>>>(N);
    long long p2 = (long long)E * 10;
    k_prop2<<<(int)((p2 + 255) / 256), 256>>>(e, E);

    long long tl = (long long)N * 32;
    k_lsm<<<(int)((tl + 255) / 256), 256>>>(b2, out, N);
}

// round 3
// speedup vs baseline: 1.3311x; 1.3311x over previous
#include <cuda_runtime.h>
#include <cuda_bf16.h>
#include <math.h>
#include <stdint.h>

// Problem constants
#define NN 100000
#define IN_DIM 500
#define HID 128
#define OUTD 40

// ---------------- scratch (device globals; allocation-free rule) -------------
__device__ int   g_stride;                 // 1 = int32 edges, 2 = int64 edges
__device__ int   g_deg [NN];
__device__ float g_dinv[NN];
__device__ __align__(16) float g_h1  [(size_t)NN * HID];
__device__ __align__(16) float g_agg1[(size_t)NN * HID];
__device__ __align__(16) float g_h2  [(size_t)NN * OUTD];
__device__ __align__(16) float g_agg2[(size_t)NN * OUTD];

// ---------------- dtype detect ----------------------------------------------
__global__ void k_detect(const int* __restrict__ e) {
    if (threadIdx.x == 0 && blockIdx.x == 0) {
        int o = 0;
        #pragma unroll
        for (int i = 0; i < 8; i++) o |= e[2 * i + 1];   // high words if int64
        g_stride = (o == 0) ? 2 : 1;
    }
}

// ---------------- degree ----------------------------------------------------
__global__ void k_deginit(int n) {
    int i = blockIdx.x * blockDim.x + threadIdx.x;
    if (i < n) g_deg[i] = 1;                 // self loop
}

__global__ void k_degcount(const int* __restrict__ e, int E) {
    int i = blockIdx.x * blockDim.x + threadIdx.x;
    if (i >= E) return;
    int st = g_stride;
    int dst = e[(size_t)(E + i) * st];
    atomicAdd(&g_deg[dst], 1);
}

__global__ void k_dinv(int n) {
    int i = blockIdx.x * blockDim.x + threadIdx.x;
    if (i < n) g_dinv[i] = rsqrtf((float)g_deg[i]);
}

// ---------------- tf32 helpers -----------------------------------------------
__device__ __forceinline__ float to_tf32(float x) {
    float r;
    asm("cvt.rna.tf32.f32 %0, %1;" : "=f"(r) : "f"(x));
    return r;
}

__device__ __forceinline__ void mma_tf32(float c[4], const uint32_t a[4], const uint32_t b[2]) {
    asm volatile(
        "mma.sync.aligned.m16n8k8.row.col.f32.tf32.tf32.f32 "
        "{%0,%1,%2,%3}, {%4,%5,%6,%7}, {%8,%9}, {%0,%1,%2,%3};"
        : "+f"(c[0]), "+f"(c[1]), "+f"(c[2]), "+f"(c[3])
        : "r"(a[0]), "r"(a[1]), "r"(a[2]), "r"(a[3]), "r"(b[0]), "r"(b[1]));
}

// ---------------- GEMM1 (tensor cores): h1 = x @ W1, fused selfinit ----------
// C tile 128x128 per CTA, K-chunks of 16 (2 mma k-steps), double buffered.
#define KC 16
#define AS_STRIDE 20     // 128 rows x 20 (pad 4) -> conflict-free A-frag LDS
#define BS_STRIDE 136    // 16 rows x 136 (pad 8) -> conflict-free B-frag LDS
#define KTILES ((IN_DIM + KC - 1) / KC)   // 32

__global__ __launch_bounds__(256, 2)
void k_gemm1_tc(const float* __restrict__ A, const float* __restrict__ B, int M) {
    __shared__ float As[2][128][AS_STRIDE];
    __shared__ float Bs[2][KC][BS_STRIDE];

    const int tid = threadIdx.x;
    const int lane = tid & 31;
    const int wid = tid >> 5;
    const int g = lane >> 2;          // 0..7
    const int tig = lane & 3;         // 0..3
    const int warp_m = wid >> 1;      // 0..3 -> 32 rows each
    const int warp_n = wid & 1;       // 0..1 -> 64 cols each
    const int rb = warp_m * 32;
    const int nb = warp_n * 64;
    const int blockRow = blockIdx.x * 128;

    float c[2][8][4];
    #pragma unroll
    for (int mt = 0; mt < 2; mt++)
        #pragma unroll
        for (int nt = 0; nt < 8; nt++)
            #pragma unroll
            for (int r = 0; r < 4; r++) c[mt][nt][r] = 0.f;

    // global load assignments
    const int ar0 = tid >> 2;                 // 0..63  (second: +64)
    const int aq0 = (tid & 3) * 4;            // 0,4,8,12
    const int br0 = tid >> 5;                 // 0..7   (second: +8)
    const int bc0 = (tid & 31) * 4;           // 0..124

    float4 vA0, vA1, vB0, vB1;

    auto load_tiles = [&](int kt) {
        vA0 = make_float4(0.f, 0.f, 0.f, 0.f);
        vA1 = vA0; vB0 = vA0; vB1 = vA0;
        int r0 = blockRow + ar0;
        int r1 = r0 + 64;
        int k0 = kt + aq0;
        if (k0 + 4 <= IN_DIM) {
            if (r0 < M) vA0 = *reinterpret_cast<const float4*>(A + (size_t)r0 * IN_DIM + k0);
            if (r1 < M) vA1 = *reinterpret_cast<const float4*>(A + (size_t)r1 * IN_DIM + k0);
        } else {
            float t0[4] = {0.f,0.f,0.f,0.f}, t1[4] = {0.f,0.f,0.f,0.f};
            #pragma unroll
            for (int q = 0; q < 4; q++) {
                if (k0 + q < IN_DIM) {
                    if (r0 < M) t0[q] = A[(size_t)r0 * IN_DIM + k0 + q];
                    if (r1 < M) t1[q] = A[(size_t)r1 * IN_DIM + k0 + q];
                }
            }
            vA0 = make_float4(t0[0], t0[1], t0[2], t0[3]);
            vA1 = make_float4(t1[0], t1[1], t1[2], t1[3]);
        }
        int bk0 = kt + br0, bk1 = bk0 + 8;
        if (bk0 < IN_DIM) vB0 = *reinterpret_cast<const float4*>(B + (size_t)bk0 * HID + bc0);
        if (bk1 < IN_DIM) vB1 = *reinterpret_cast<const float4*>(B + (size_t)bk1 * HID + bc0);
        // convert once here (instead of per-use in the inner loop)
        vA0.x = to_tf32(vA0.x); vA0.y = to_tf32(vA0.y); vA0.z = to_tf32(vA0.z); vA0.w = to_tf32(vA0.w);
        vA1.x = to_tf32(vA1.x); vA1.y = to_tf32(vA1.y); vA1.z = to_tf32(vA1.z); vA1.w = to_tf32(vA1.w);
        vB0.x = to_tf32(vB0.x); vB0.y = to_tf32(vB0.y); vB0.z = to_tf32(vB0.z); vB0.w = to_tf32(vB0.w);
        vB1.x = to_tf32(vB1.x); vB1.y = to_tf32(vB1.y); vB1.z = to_tf32(vB1.z); vB1.w = to_tf32(vB1.w);
    };

    auto store_tiles = [&](int buf) {
        *reinterpret_cast<float4*>(&As[buf][ar0][aq0])      = vA0;
        *reinterpret_cast<float4*>(&As[buf][ar0 + 64][aq0]) = vA1;
        *reinterpret_cast<float4*>(&Bs[buf][br0][bc0])      = vB0;
        *reinterpret_cast<float4*>(&Bs[buf][br0 + 8][bc0])  = vB1;
    };

    load_tiles(0);
    store_tiles(0);
    __syncthreads();

    int buf = 0;
    for (int it = 0; it < KTILES; it++) {
        if (it + 1 < KTILES) load_tiles((it + 1) * KC);

        #pragma unroll
        for (int ks = 0; ks < 2; ks++) {
            const int k0 = ks * 8;
            uint32_t af[2][4], bf[8][2];
            #pragma unroll
            for (int mt = 0; mt < 2; mt++) {
                int r = rb + mt * 16 + g;
                af[mt][0] = __float_as_uint(As[buf][r    ][k0 + tig]);
                af[mt][1] = __float_as_uint(As[buf][r + 8][k0 + tig]);
                af[mt][2] = __float_as_uint(As[buf][r    ][k0 + tig + 4]);
                af[mt][3] = __float_as_uint(As[buf][r + 8][k0 + tig + 4]);
            }
            #pragma unroll
            for (int nt = 0; nt < 8; nt++) {
                int cN = nb + nt * 8 + g;
                bf[nt][0] = __float_as_uint(Bs[buf][k0 + tig    ][cN]);
                bf[nt][1] = __float_as_uint(Bs[buf][k0 + tig + 4][cN]);
            }
            #pragma unroll
            for (int mt = 0; mt < 2; mt++)
                #pragma unroll
                for (int nt = 0; nt < 8; nt++)
                    mma_tf32(c[mt][nt], af[mt], bf[nt]);
        }

        if (it + 1 < KTILES) store_tiles(buf ^ 1);
        __syncthreads();
        buf ^= 1;
    }

    // epilogue: write h1 and fused self-loop agg1 = h1 * dinv^2
    #pragma unroll
    for (int mt = 0; mt < 2; mt++) {
        int r0 = blockRow + rb + mt * 16 + g;
        int r1 = r0 + 8;
        float s0 = 0.f, s1 = 0.f;
        if (r0 < M) { float d = g_dinv[r0]; s0 = d * d; }
        if (r1 < M) { float d = g_dinv[r1]; s1 = d * d; }
        #pragma unroll
        for (int nt = 0; nt < 8; nt++) {
            int col = nb + nt * 8 + 2 * tig;
            if (r0 < M) {
                float2 v = make_float2(c[mt][nt][0], c[mt][nt][1]);
                *reinterpret_cast<float2*>(g_h1   + (size_t)r0 * HID + col) = v;
                *reinterpret_cast<float2*>(g_agg1 + (size_t)r0 * HID + col) = make_float2(v.x * s0, v.y * s0);
            }
            if (r1 < M) {
                float2 v = make_float2(c[mt][nt][2], c[mt][nt][3]);
                *reinterpret_cast<float2*>(g_h1   + (size_t)r1 * HID + col) = v;
                *reinterpret_cast<float2*>(g_agg2 == nullptr ? nullptr : g_agg1 + (size_t)r1 * HID + col) = make_float2(v.x * s1, v.y * s1);
            }
        }
    }
}

// ---------------- edge propagation, F=128: one warp per edge -----------------
__global__ __launch_bounds__(256)
void k_prop1(const int* __restrict__ e, int E) {
    int warpId = (blockIdx.x * blockDim.x + threadIdx.x) >> 5;
    int lane = threadIdx.x & 31;
    if (warpId >= E) return;
    int st = g_stride;
    int src = e[(size_t)warpId * st];
    int dst = e[(size_t)(E + warpId) * st];
    float nrm = g_dinv[src] * g_dinv[dst];
    float4 v = reinterpret_cast<const float4*>(g_h1 + (size_t)src * HID)[lane];
    v.x *= nrm; v.y *= nrm; v.z *= nrm; v.w *= nrm;
    float* dp = g_agg1 + (size_t)dst * HID + lane * 4;
    asm volatile("red.global.add.v4.f32 [%0], {%1,%2,%3,%4};"
                 :: "l"(dp), "f"(v.x), "f"(v.y), "f"(v.z), "f"(v.w) : "memory");
}

// ---------------- bias + relu (writes back into g_h1) ------------------------
__global__ void k_bias_relu(const float* __restrict__ b1, int n) {
    int i = blockIdx.x * blockDim.x + threadIdx.x;   // over n * 32 float4s
    if (i >= n * (HID / 4)) return;
    int c4 = (i & 31) * 4;
    float4 v = reinterpret_cast<const float4*>(g_agg1)[i];
    float4 b = *reinterpret_cast<const float4*>(b1 + c4);
    v.x = fmaxf(v.x + b.x, 0.f); v.y = fmaxf(v.y + b.y, 0.f);
    v.z = fmaxf(v.z + b.z, 0.f); v.w = fmaxf(v.w + b.w, 0.f);
    reinterpret_cast<float4*>(g_h1)[i] = v;
}

// ---------------- GEMM2: h2 = relu(h) @ W2, fused selfinit2 ------------------
__global__ __launch_bounds__(320)
void k_gemm2(const float* __restrict__ W2, int M) {
    __shared__ __align__(16) float sW[HID * OUTD];   // 20 KB
    int tid = threadIdx.x;
    for (int i = tid; i < HID * OUTD; i += 320) sW[i] = W2[i];
    __syncthreads();

    int g = tid % 10;                 // col group (4 cols)
    int rl = tid / 10;                // 0..31
    int row = blockIdx.x * 32 + rl;
    if (row >= M) return;
    const float* hr = g_h1 + (size_t)row * HID;
    float4 acc = make_float4(0.f, 0.f, 0.f, 0.f);
    #pragma unroll 8
    for (int k = 0; k < HID; k++) {
        float hv = __ldg(hr + k);
        float4 w = *reinterpret_cast<const float4*>(&sW[k * OUTD + g * 4]);
        acc.x += hv * w.x; acc.y += hv * w.y; acc.z += hv * w.z; acc.w += hv * w.w;
    }
    *reinterpret_cast<float4*>(g_h2 + (size_t)row * OUTD + g * 4) = acc;
    float d = g_dinv[row]; float s = d * d;
    acc.x *= s; acc.y *= s; acc.z *= s; acc.w *= s;
    *reinterpret_cast<float4*>(g_agg2 + (size_t)row * OUTD + g * 4) = acc;
}

// ---------------- edge propagation, F=40: thread per (edge, float4) ----------
__global__ __launch_bounds__(256)
void k_prop2(const int* __restrict__ e, int E) {
    int idx = blockIdx.x * blockDim.x + threadIdx.x;
    if (idx >= E * 10) return;
    int ed = idx / 10;
    int g = idx - ed * 10;
    int st = g_stride;
    int src = e[(size_t)ed * st];
    int dst = e[(size_t)(E + ed) * st];
    float nrm = g_dinv[src] * g_dinv[dst];
    float4 v = reinterpret_cast<const float4*>(g_h2 + (size_t)src * OUTD)[g];
    v.x *= nrm; v.y *= nrm; v.z *= nrm; v.w *= nrm;
    float* dp = g_agg2 + (size_t)dst * OUTD + g * 4;
    asm volatile("red.global.add.v4.f32 [%0], {%1,%2,%3,%4};"
                 :: "l"(dp), "f"(v.x), "f"(v.y), "f"(v.z), "f"(v.w) : "memory");
}

// ---------------- bias + log_softmax: warp per row ---------------------------
__global__ __launch_bounds__(256)
void k_lsm(const float* __restrict__ b2, float* __restrict__ out, int n) {
    int row = (blockIdx.x * blockDim.x + threadIdx.x) >> 5;
    int lane = threadIdx.x & 31;
    if (row >= n) return;
    const float* a = g_agg2 + (size_t)row * OUTD;
    float v0 = a[lane] + b2[lane];
    float v1 = (lane < 8) ? (a[lane + 32] + b2[lane + 32]) : -INFINITY;
    float m = fmaxf(v0, v1);
    #pragma unroll
    for (int o = 16; o; o >>= 1) m = fmaxf(m, __shfl_xor_sync(0xffffffffu, m, o));
    float s = expf(v0 - m) + ((lane < 8) ? expf(v1 - m) : 0.f);
    #pragma unroll
    for (int o = 16; o; o >>= 1) s += __shfl_xor_sync(0xffffffffu, s, o);
    float l = m + logf(s);
    out[(size_t)row * OUTD + lane] = v0 - l;
    if (lane < 8) out[(size_t)row * OUTD + 32 + lane] = v1 - l;
}

// ---------------- launch -----------------------------------------------------
extern "C" void kernel_launch(void* const* d_in, const int* in_sizes, int n_in,
                              void* d_out, int out_size) {
    const float* x  = (const float*)d_in[0];
    const int*   e  = (const int*)d_in[1];
    const float* W1 = (const float*)d_in[2];
    const float* b1 = (const float*)d_in[3];
    const float* W2 = (const float*)d_in[4];
    const float* b2 = (const float*)d_in[5];
    float* out = (float*)d_out;

    int N = in_sizes[0] / IN_DIM;     // 100000
    int E = in_sizes[1] / 2;          // 1600000

    k_detect<<<1, 32>>>(e);
    k_deginit<<<(N + 255) / 256, 256>>>(N);
    k_degcount<<<(E + 255) / 256, 256>>>(e, E);
    k_dinv<<<(N + 255) / 256, 256>>>(N);

    k_gemm1_tc<<<(N + 127) / 128, 256>>>(x, W1, N);

    long long p1 = (long long)E * 32;
    k_prop1<<<(int)((p1 + 255) / 256), 256>>>(e, E);
    int t1 = N * (HID / 4);
    k_bias_relu<<<(t1 + 255) / 256, 256>>>(b1, N);

    k_gemm2<<<(N + 31) / 32, 320>>>(W2, N);

    long long p2 = (long long)E * 10;
    k_prop2<<<(int)((p2 + 255) / 256), 256>>>(e, E);

    long long tl = (long long)N * 32;
    k_lsm<<<(int)((tl + 255) / 256), 256>>>(b2, out, N);
}